// round 5
// baseline (speedup 1.0000x reference)
#include <cuda_runtime.h>

#define D      64
#define KCODES 1024
#define NTOK   65536
#define HW     4096

// Scratch (device globals — no allocation allowed).
__device__ float g_E[KCODES * D * 2];  // codebook fragments, hi/lo interleaved
__device__ float g_sse[KCODES];        // ||e_k||^2
__device__ float g_pd[4 * NTOK];       // per-quarter best dist
__device__ int   g_pi[4 * NTOK];       // per-quarter best idx

__device__ __forceinline__ float tf32_rna(float x) {
    unsigned u;
    asm("cvt.rna.tf32.f32 %0, %1;" : "=r"(u) : "f"(x));
    return __uint_as_float(u);
}

// C += A(tf32 16x8) * B(tf32 8x8), fp32 accumulate.
__device__ __forceinline__ void mma_tf32(float c[4], const float* a, float b0, float b1) {
    asm("mma.sync.aligned.m16n8k8.row.col.f32.tf32.tf32.f32 "
        "{%0,%1,%2,%3}, {%4,%5,%6,%7}, {%8,%9}, {%0,%1,%2,%3};"
        : "+f"(c[0]), "+f"(c[1]), "+f"(c[2]), "+f"(c[3])
        : "r"(__float_as_uint(a[0])), "r"(__float_as_uint(a[1])),
          "r"(__float_as_uint(a[2])), "r"(__float_as_uint(a[3])),
          "r"(__float_as_uint(b0)),   "r"(__float_as_uint(b1)));
}

// ---------------- prep: codebook -> interleaved hi/lo B-fragments + sse ----
// Slot for code n, dim k:  base = ((ntile*8 + kstep)*32 + lane)*4
//   [base+j]   = hi,  [base+2+j] = lo   (j = (k>>2)&1)
// so one float4 per (ntile,kstep,lane) = {bh0, bh1, bl0, bl1}.
__global__ void vq_prep(const float* __restrict__ cb) {
    int tid = blockIdx.x * blockDim.x + threadIdx.x;   // 65536 = 1024*64
    int n = tid >> 6, k = tid & 63;
    float e  = cb[n * D + k];
    float hi = tf32_rna(e);
    float lo = e - hi;
    int ntile = n >> 3, kstep = k >> 3;
    int lane  = ((n & 7) << 2) + (k & 3);
    int j     = (k >> 2) & 1;
    int base  = ((ntile * 8 + kstep) * 32 + lane) * 4;
    g_E[base + j]     = hi;
    g_E[base + 2 + j] = lo;
    if (k == 0) {
        const float* row = cb + n * D;
        float s = 0.0f;
        for (int d = 0; d < D; ++d) s += row[d] * row[d];
        g_sse[n] = s;
    }
}

// ---------------- main: 3xTF32 GEMM + argmin over a code quarter ----------
__global__ void __launch_bounds__(256, 1)
vq_main(const float* __restrict__ input) {
    extern __shared__ float sm[];
    float* sE   = sm;            // 32768 floats (256 codes, frag order, hi/lo fused)
    float* sSse = sm + 32768;    // 256

    const int q   = blockIdx.y;  // code quarter
    const int tid = threadIdx.x;

    // Stage this quarter's fragments (contiguous 32768-float range per quarter).
    {
        const float4* src = (const float4*)g_E + q * 8192;
        float4* dst = (float4*)sE;
        #pragma unroll
        for (int i = 0; i < 32; ++i)
            dst[tid + i * 256] = src[tid + i * 256];
        sSse[tid] = g_sse[q * 256 + tid];
    }
    __syncthreads();

    const int w    = tid >> 5;
    const int lane = tid & 31;
    const int grp  = lane >> 5 ? 0 : (lane >> 2);  // lane>>2 (0..7)
    const int cb4  = lane & 3;

    #pragma unroll 1
    for (int p = 0; p < 8; ++p) {
        // This warp's pair of 16-token m-tiles: 32 tokens starting at base.
        const int base = blockIdx.x * 2048 + (w * 8 + p) * 32;

        float Ahi[2][32], Alo[2][32];
        float ssx[2][2];
        #pragma unroll
        for (int mt = 0; mt < 2; ++mt) {
            const int row0 = base + mt * 16 + grp;   // + row0+8 = second half
            const int b    = row0 >> 12;
            const int hw   = row0 & (HW - 1);
            const float* p0 = input + (size_t)b * D * HW + hw;
            const float* p1 = p0 + 8;
            float s0 = 0.0f, s1 = 0.0f;
            #pragma unroll
            for (int ks = 0; ks < 8; ++ks) {
                const int d0 = ks * 8 + cb4;
                float x00 = p0[(size_t)d0 * HW];
                float x10 = p1[(size_t)d0 * HW];
                float x01 = p0[(size_t)(d0 + 4) * HW];
                float x11 = p1[(size_t)(d0 + 4) * HW];
                s0 = fmaf(x00, x00, s0);  s0 = fmaf(x01, x01, s0);
                s1 = fmaf(x10, x10, s1);  s1 = fmaf(x11, x11, s1);
                float h;
                h = tf32_rna(x00); Ahi[mt][ks*4+0] = h; Alo[mt][ks*4+0] = x00 - h;
                h = tf32_rna(x10); Ahi[mt][ks*4+1] = h; Alo[mt][ks*4+1] = x10 - h;
                h = tf32_rna(x01); Ahi[mt][ks*4+2] = h; Alo[mt][ks*4+2] = x01 - h;
                h = tf32_rna(x11); Ahi[mt][ks*4+3] = h; Alo[mt][ks*4+3] = x11 - h;
            }
            // ssx is common-mode per token — any fp32-accurate order works.
            s0 += __shfl_xor_sync(0xffffffffu, s0, 1);
            s0 += __shfl_xor_sync(0xffffffffu, s0, 2);
            s1 += __shfl_xor_sync(0xffffffffu, s1, 1);
            s1 += __shfl_xor_sync(0xffffffffu, s1, 2);
            ssx[mt][0] = s0;
            ssx[mt][1] = s1;
        }

        float best[2][2] = {{3.4e38f, 3.4e38f}, {3.4e38f, 3.4e38f}};
        int   bidx[2][2] = {{0, 0}, {0, 0}};

        #pragma unroll 1
        for (int ng = 0; ng < 32; ng += 2) {    // 32 n-tiles per quarter
            float C[2][2][4];                    // [mt][u][frag]
            #pragma unroll
            for (int mt = 0; mt < 2; ++mt)
                #pragma unroll
                for (int u = 0; u < 2; ++u)
                    #pragma unroll
                    for (int v = 0; v < 4; ++v) C[mt][u][v] = 0.0f;

            #pragma unroll
            for (int ks = 0; ks < 8; ++ks) {
                #pragma unroll
                for (int u = 0; u < 2; ++u) {
                    // One LDS.128: {bh0, bh1, bl0, bl1}, reused by both m-tiles.
                    float4 B = *(const float4*)&sE[(((ng + u) * 8 + ks) * 32 + lane) * 4];
                    #pragma unroll
                    for (int mt = 0; mt < 2; ++mt) {
                        mma_tf32(C[mt][u], &Ahi[mt][ks * 4], B.x, B.y);  // hi*hi
                        mma_tf32(C[mt][u], &Ahi[mt][ks * 4], B.z, B.w);  // hi*lo
                        mma_tf32(C[mt][u], &Alo[mt][ks * 4], B.x, B.y);  // lo*hi
                    }
                }
            }

            #pragma unroll
            for (int u = 0; u < 2; ++u) {
                const int ncol = (ng + u) * 8 + 2 * cb4;
                float2 ss = *(const float2*)&sSse[ncol];
                const int kg = q * 256 + ncol;
                #pragma unroll
                for (int mt = 0; mt < 2; ++mt) {
                    float d00 = (ssx[mt][0] + ss.x) - 2.0f * C[mt][u][0];
                    float d01 = (ssx[mt][0] + ss.y) - 2.0f * C[mt][u][1];
                    float d10 = (ssx[mt][1] + ss.x) - 2.0f * C[mt][u][2];
                    float d11 = (ssx[mt][1] + ss.y) - 2.0f * C[mt][u][3];
                    if (d00 < best[mt][0]) { best[mt][0] = d00; bidx[mt][0] = kg;     }
                    if (d01 < best[mt][0]) { best[mt][0] = d01; bidx[mt][0] = kg + 1; }
                    if (d10 < best[mt][1]) { best[mt][1] = d10; bidx[mt][1] = kg;     }
                    if (d11 < best[mt][1]) { best[mt][1] = d11; bidx[mt][1] = kg + 1; }
                }
            }
        }

        // Reduce over the 4 lanes of each row group; ties -> lower index.
        #pragma unroll
        for (int mt = 0; mt < 2; ++mt) {
            #pragma unroll
            for (int h = 0; h < 2; ++h) {
                #pragma unroll
                for (int o = 1; o <= 2; o <<= 1) {
                    float od = __shfl_xor_sync(0xffffffffu, best[mt][h], o);
                    int   oi = __shfl_xor_sync(0xffffffffu, bidx[mt][h], o);
                    if (od < best[mt][h] || (od == best[mt][h] && oi < bidx[mt][h])) {
                        best[mt][h] = od; bidx[mt][h] = oi;
                    }
                }
            }
        }
        if (cb4 == 0) {
            #pragma unroll
            for (int mt = 0; mt < 2; ++mt) {
                const int r = base + mt * 16 + grp;
                g_pd[q * NTOK + r]     = best[mt][0];
                g_pi[q * NTOK + r]     = bidx[mt][0];
                g_pd[q * NTOK + r + 8] = best[mt][1];
                g_pi[q * NTOK + r + 8] = bidx[mt][1];
            }
        }
    }
}

// ---------------- combine: reduce 4 quarters, gather, NCHW scatter ---------
__global__ void vq_combine(const float* __restrict__ cb, float* __restrict__ out) {
    const int t = blockIdx.x * blockDim.x + threadIdx.x;
    float best = g_pd[t];
    int   bi   = g_pi[t];
    #pragma unroll
    for (int qq = 1; qq < 4; ++qq) {   // ascending q => strict < keeps lowest idx
        float d = g_pd[qq * NTOK + t];
        int   i = g_pi[qq * NTOK + t];
        if (d < best) { best = d; bi = i; }
    }
    const int b = t >> 12, hw = t & (HW - 1);
    const float4* e  = (const float4*)cb + bi * (D / 4);
    float*        op = out + (size_t)b * D * HW + hw;
    #pragma unroll
    for (int j = 0; j < D / 4; ++j) {
        float4 v = __ldg(e + j);
        op[(4 * j + 0) * HW] = v.x;
        op[(4 * j + 1) * HW] = v.y;
        op[(4 * j + 2) * HW] = v.z;
        op[(4 * j + 3) * HW] = v.w;
    }
}

extern "C" void kernel_launch(void* const* d_in, const int* in_sizes, int n_in,
                              void* d_out, int out_size) {
    const float* input    = (const float*)d_in[0];   // [16, 64, 64, 64] fp32 NCHW
    const float* codebook = (const float*)d_in[1];   // [1024, 64] fp32
    float*       out      = (float*)d_out;

    size_t smem_bytes = (size_t)(32768 + 256) * sizeof(float);  // 132096 B
    cudaFuncSetAttribute(vq_main, cudaFuncAttributeMaxDynamicSharedMemorySize,
                         (int)smem_bytes);

    vq_prep<<<64, 1024>>>(codebook);
    vq_main<<<dim3(32, 4), 256, smem_bytes>>>(input);
    vq_combine<<<256, 256>>>(codebook, out);
}

// round 6
// speedup vs baseline: 1.0078x; 1.0078x over previous
#include <cuda_runtime.h>

#define D      64
#define KCODES 1024
#define NTOK   65536
#define HW     4096

// Scratch (device globals — no allocation allowed).
__device__ float g_pd[4 * NTOK];       // per-quarter best dist
__device__ int   g_pi[4 * NTOK];       // per-quarter best idx

__device__ __forceinline__ float tf32_rna(float x) {
    unsigned u;
    asm("cvt.rna.tf32.f32 %0, %1;" : "=r"(u) : "f"(x));
    return __uint_as_float(u);
}

// C += A(tf32 16x8) * B(tf32 8x8), fp32 accumulate.
__device__ __forceinline__ void mma_tf32(float c[4], const float* a, float b0, float b1) {
    asm("mma.sync.aligned.m16n8k8.row.col.f32.tf32.tf32.f32 "
        "{%0,%1,%2,%3}, {%4,%5,%6,%7}, {%8,%9}, {%0,%1,%2,%3};"
        : "+f"(c[0]), "+f"(c[1]), "+f"(c[2]), "+f"(c[3])
        : "r"(__float_as_uint(a[0])), "r"(__float_as_uint(a[1])),
          "r"(__float_as_uint(a[2])), "r"(__float_as_uint(a[3])),
          "r"(__float_as_uint(b0)),   "r"(__float_as_uint(b1)));
}

// ---------------- main: in-CTA prep + 3xTF32 GEMM + argmin over a quarter --
// B-frag slot (local code n0 in quarter, dim k):
//   base = ((ntile*8 + kstep)*32 + lane)*4 ; [base+j]=hi, [base+2+j]=lo
//   ntile=n0>>3, kstep=k>>3, lane=((n0&7)<<2)+(k&3), j=(k>>2)&1
__global__ void __launch_bounds__(256, 1)
vq_main(const float* __restrict__ input, const float* __restrict__ cb) {
    extern __shared__ float sm[];
    float* sE   = sm;            // 32768 floats (256 codes, frag order, hi/lo fused)
    float* sSse = sm + 32768;    // 256

    const int q   = blockIdx.y;  // code quarter
    const int tid = threadIdx.x;

    // ---- fused prep: convert this quarter's 256 codes to hi/lo fragments ----
    {
        const float* row = cb + (q * 256 + tid) * D;
        const int ntile = tid >> 3;
        const int lbase = (tid & 7) << 2;
        #pragma unroll
        for (int k = 0; k < D; ++k) {
            float e  = row[k];
            float hi = tf32_rna(e);
            float lo = e - hi;
            int kstep = k >> 3;
            int lane  = lbase + (k & 3);
            int j     = (k >> 2) & 1;
            int base  = ((ntile * 8 + kstep) * 32 + lane) * 4;
            sE[base + j]     = hi;
            sE[base + 2 + j] = lo;
        }
        // sse: same sequential source as the previously-passing prep kernel.
        float s = 0.0f;
        for (int d = 0; d < D; ++d) s += row[d] * row[d];
        sSse[tid] = s;
    }
    __syncthreads();

    const int w    = tid >> 5;
    const int lane = tid & 31;
    const int grp  = lane >> 2;   // 0..7
    const int cb4  = lane & 3;    // 0..3

    #pragma unroll 1
    for (int p = 0; p < 8; ++p) {
        // This warp's pair of 16-token m-tiles: 32 tokens starting at base.
        const int base = blockIdx.x * 2048 + (w * 8 + p) * 32;

        float Ahi[2][32], Alo[2][32];
        float ssx[2][2];
        #pragma unroll
        for (int mt = 0; mt < 2; ++mt) {
            const int row0 = base + mt * 16 + grp;
            const int b    = row0 >> 12;
            const int hw   = row0 & (HW - 1);
            const float* p0 = input + (size_t)b * D * HW + hw;
            const float* p1 = p0 + 8;
            float s0 = 0.0f, s1 = 0.0f;
            #pragma unroll
            for (int ks = 0; ks < 8; ++ks) {
                const int d0 = ks * 8 + cb4;
                float x00 = p0[(size_t)d0 * HW];
                float x10 = p1[(size_t)d0 * HW];
                float x01 = p0[(size_t)(d0 + 4) * HW];
                float x11 = p1[(size_t)(d0 + 4) * HW];
                s0 = fmaf(x00, x00, s0);  s0 = fmaf(x01, x01, s0);
                s1 = fmaf(x10, x10, s1);  s1 = fmaf(x11, x11, s1);
                float h;
                h = tf32_rna(x00); Ahi[mt][ks*4+0] = h; Alo[mt][ks*4+0] = x00 - h;
                h = tf32_rna(x10); Ahi[mt][ks*4+1] = h; Alo[mt][ks*4+1] = x10 - h;
                h = tf32_rna(x01); Ahi[mt][ks*4+2] = h; Alo[mt][ks*4+2] = x01 - h;
                h = tf32_rna(x11); Ahi[mt][ks*4+3] = h; Alo[mt][ks*4+3] = x11 - h;
            }
            // ssx is common-mode per token — any fp32-accurate order works.
            s0 += __shfl_xor_sync(0xffffffffu, s0, 1);
            s0 += __shfl_xor_sync(0xffffffffu, s0, 2);
            s1 += __shfl_xor_sync(0xffffffffu, s1, 1);
            s1 += __shfl_xor_sync(0xffffffffu, s1, 2);
            ssx[mt][0] = s0;
            ssx[mt][1] = s1;
        }

        float best[2][2] = {{3.4e38f, 3.4e38f}, {3.4e38f, 3.4e38f}};
        int   bidx[2][2] = {{0, 0}, {0, 0}};

        #pragma unroll 1
        for (int ng = 0; ng < 32; ng += 2) {
            // Per-plane accumulators: 12 independent MMA chains per thread.
            float Chh[2][2][4], Chl[2][2][4], Clh[2][2][4];
            #pragma unroll
            for (int mt = 0; mt < 2; ++mt)
                #pragma unroll
                for (int u = 0; u < 2; ++u)
                    #pragma unroll
                    for (int v = 0; v < 4; ++v) {
                        Chh[mt][u][v] = 0.0f;
                        Chl[mt][u][v] = 0.0f;
                        Clh[mt][u][v] = 0.0f;
                    }

            #pragma unroll
            for (int ks = 0; ks < 8; ++ks) {
                #pragma unroll
                for (int u = 0; u < 2; ++u) {
                    // One LDS.128: {bh0, bh1, bl0, bl1}, reused by both m-tiles.
                    float4 B = *(const float4*)&sE[(((ng + u) * 8 + ks) * 32 + lane) * 4];
                    #pragma unroll
                    for (int mt = 0; mt < 2; ++mt) {
                        mma_tf32(Chh[mt][u], &Ahi[mt][ks * 4], B.x, B.y);  // hi*hi
                        mma_tf32(Chl[mt][u], &Ahi[mt][ks * 4], B.z, B.w);  // hi*lo
                        mma_tf32(Clh[mt][u], &Alo[mt][ks * 4], B.x, B.y);  // lo*hi
                    }
                }
            }

            #pragma unroll
            for (int u = 0; u < 2; ++u) {
                const int ncol = (ng + u) * 8 + 2 * cb4;
                float2 ss = *(const float2*)&sSse[ncol];
                const int kg = q * 256 + ncol;
                #pragma unroll
                for (int mt = 0; mt < 2; ++mt) {
                    float c0 = (Chh[mt][u][0] + Chl[mt][u][0]) + Clh[mt][u][0];
                    float c1 = (Chh[mt][u][1] + Chl[mt][u][1]) + Clh[mt][u][1];
                    float c2 = (Chh[mt][u][2] + Chl[mt][u][2]) + Clh[mt][u][2];
                    float c3 = (Chh[mt][u][3] + Chl[mt][u][3]) + Clh[mt][u][3];
                    float d00 = (ssx[mt][0] + ss.x) - 2.0f * c0;
                    float d01 = (ssx[mt][0] + ss.y) - 2.0f * c1;
                    float d10 = (ssx[mt][1] + ss.x) - 2.0f * c2;
                    float d11 = (ssx[mt][1] + ss.y) - 2.0f * c3;
                    if (d00 < best[mt][0]) { best[mt][0] = d00; bidx[mt][0] = kg;     }
                    if (d01 < best[mt][0]) { best[mt][0] = d01; bidx[mt][0] = kg + 1; }
                    if (d10 < best[mt][1]) { best[mt][1] = d10; bidx[mt][1] = kg;     }
                    if (d11 < best[mt][1]) { best[mt][1] = d11; bidx[mt][1] = kg + 1; }
                }
            }
        }

        // Reduce over the 4 lanes of each row group; ties -> lower index.
        #pragma unroll
        for (int mt = 0; mt < 2; ++mt) {
            #pragma unroll
            for (int h = 0; h < 2; ++h) {
                #pragma unroll
                for (int o = 1; o <= 2; o <<= 1) {
                    float od = __shfl_xor_sync(0xffffffffu, best[mt][h], o);
                    int   oi = __shfl_xor_sync(0xffffffffu, bidx[mt][h], o);
                    if (od < best[mt][h] || (od == best[mt][h] && oi < bidx[mt][h])) {
                        best[mt][h] = od; bidx[mt][h] = oi;
                    }
                }
            }
        }
        if (cb4 == 0) {
            #pragma unroll
            for (int mt = 0; mt < 2; ++mt) {
                const int r = base + mt * 16 + grp;
                g_pd[q * NTOK + r]     = best[mt][0];
                g_pi[q * NTOK + r]     = bidx[mt][0];
                g_pd[q * NTOK + r + 8] = best[mt][1];
                g_pi[q * NTOK + r + 8] = bidx[mt][1];
            }
        }
    }
}

// ---------------- combine: reduce 4 quarters, gather, NCHW scatter ---------
__global__ void vq_combine(const float* __restrict__ cb, float* __restrict__ out) {
    const int t = blockIdx.x * blockDim.x + threadIdx.x;
    float best = g_pd[t];
    int   bi   = g_pi[t];
    #pragma unroll
    for (int qq = 1; qq < 4; ++qq) {   // ascending q => strict < keeps lowest idx
        float d = g_pd[qq * NTOK + t];
        int   i = g_pi[qq * NTOK + t];
        if (d < best) { best = d; bi = i; }
    }
    const int b = t >> 12, hw = t & (HW - 1);
    const float4* e  = (const float4*)cb + bi * (D / 4);
    float*        op = out + (size_t)b * D * HW + hw;
    #pragma unroll
    for (int j = 0; j < D / 4; ++j) {
        float4 v = __ldg(e + j);
        op[(4 * j + 0) * HW] = v.x;
        op[(4 * j + 1) * HW] = v.y;
        op[(4 * j + 2) * HW] = v.z;
        op[(4 * j + 3) * HW] = v.w;
    }
}

extern "C" void kernel_launch(void* const* d_in, const int* in_sizes, int n_in,
                              void* d_out, int out_size) {
    const float* input    = (const float*)d_in[0];   // [16, 64, 64, 64] fp32 NCHW
    const float* codebook = (const float*)d_in[1];   // [1024, 64] fp32
    float*       out      = (float*)d_out;

    size_t smem_bytes = (size_t)(32768 + 256) * sizeof(float);  // 132096 B
    cudaFuncSetAttribute(vq_main, cudaFuncAttributeMaxDynamicSharedMemorySize,
                         (int)smem_bytes);

    vq_main<<<dim3(32, 4), 256, smem_bytes>>>(input, codebook);
    vq_combine<<<256, 256>>>(codebook, out);
}

// round 10
// speedup vs baseline: 1.6383x; 1.6257x over previous
#include <cuda_runtime.h>
#include <cuda_fp16.h>
#include <cstdint>

#define D       64
#define HW      4096
#define KCODES  1024

// codebook pre-scale 2^10 (exact); dot scale-back 2^-10 (exact)
#define ESCALE   1024.0f
#define EINV     0.0009765625f

// ---------------- device scratch (no allocation allowed) -------------------
// B fragments: [half(2)][ntile(64)][kstep(4)][lane(32)] x uint4 {bh0,bh1,bl0,bl1}
__device__ __half g_E[KCODES * D * 2];   // 256KB
__device__ float  g_sse[KCODES];

// pack two floats to fp16x2 (x0 -> low half)
__device__ __forceinline__ uint32_t packh(float x0, float x1) {
    uint32_t r;
    asm("cvt.rn.f16x2.f32 %0, %1, %2;" : "=r"(r) : "f"(x1), "f"(x0));
    return r;
}

// C += A(f16 16x16) * B(f16 16x8), fp32 accumulate.
__device__ __forceinline__ void mma_f16(float c[4], const uint32_t* a,
                                        uint32_t b0, uint32_t b1) {
    asm("mma.sync.aligned.m16n8k16.row.col.f32.f16.f16.f32 "
        "{%0,%1,%2,%3}, {%4,%5,%6,%7}, {%8,%9}, {%0,%1,%2,%3};"
        : "+f"(c[0]), "+f"(c[1]), "+f"(c[2]), "+f"(c[3])
        : "r"(a[0]), "r"(a[1]), "r"(a[2]), "r"(a[3]), "r"(b0), "r"(b1));
}

// ---------------- prep: codebook -> f16 hi/lo B-fragments (scaled) + sse ---
// m16n8k16 .col B-frag: b0 holds k={2*cb4, 2*cb4+1}, b1 holds k+8, col n = lane>>2.
__global__ void vq_prep(const float* __restrict__ cb) {
    int id = blockIdx.x * blockDim.x + threadIdx.x;   // 65536 = 1024*64
    int n = id >> 6, k = id & 63;
    float es = cb[id] * ESCALE;                 // exact power-of-2 scale
    __half hi = __float2half(es);
    __half lo = __float2half(es - __half2float(hi));
    int ntile = n >> 3, nrow = n & 7;
    int kstep = k >> 4, kin = k & 15;
    int j    = kin >> 3;          // reg index (b0/b1)
    int cb4  = (kin & 7) >> 1;
    int elem = k & 1;
    int slot = (ntile * 4 + kstep) * 32 + nrow * 4 + cb4;   // 16B slots
    g_E[slot * 8 + j * 2 + elem]     = hi;
    g_E[slot * 8 + 4 + j * 2 + elem] = lo;
    if (k == 0) {   // sequential row sum, unscaled — same order as passing kernels
        const float* r = cb + n * D;
        float s = 0.0f;
        for (int d0 = 0; d0 < D; ++d0) s += r[d0] * r[d0];
        g_sse[n] = s;
    }
}

#define SMEM_REQ (131072 + 4096)

// ---------------- main: 3xFP16 GEMM + argmin over ALL codes + output -------
__global__ void __launch_bounds__(256, 1)
vq_main(const float* __restrict__ input, const float* __restrict__ cb,
        float* __restrict__ out) {
    extern __shared__ char smraw[];
    uint4* sB   = (uint4*)smraw;                 // 8192 slots = 128KB (one half)
    float* sSse = (float*)(smraw + 131072);      // 1024 floats

    const int tid  = threadIdx.x;
    const int w    = tid >> 5;
    const int lane = tid & 31;
    const int grp  = lane >> 2;   // 0..7
    const int cb4  = lane & 3;    // 0..3

    // stage sse once (visibility covered by the first staging __syncthreads)
    #pragma unroll
    for (int i = 0; i < 4; ++i) sSse[tid + i * 256] = g_sse[tid + i * 256];

    #pragma unroll 1
    for (int p = 0; p < 2; ++p) {
        const int base = blockIdx.x * 512 + w * 64 + p * 32;

        // ---- A fragments: 2 m-tiles (32 tokens), fp16 hi/lo planes ----
        uint32_t Ahi[2][16], Alo[2][16];
        float ssx[2][2];
        #pragma unroll
        for (int mt = 0; mt < 2; ++mt) {
            const int row0 = base + mt * 16 + grp;
            const int b    = row0 >> 12;
            const int hw   = row0 & (HW - 1);
            const float* p0 = input + (size_t)b * D * HW + hw;
            const float* p1 = p0 + 8;
            float s0 = 0.0f, s1 = 0.0f;
            #pragma unroll
            for (int ks = 0; ks < 4; ++ks) {
                const int k0 = ks * 16 + 2 * cb4;
                float xa, xb;
                // a0: row grp, k={k0,k0+1}
                xa = p0[(size_t)k0 * HW];        xb = p0[(size_t)(k0 + 1) * HW];
                s0 = fmaf(xa, xa, s0);           s0 = fmaf(xb, xb, s0);
                {
                    uint32_t h = packh(xa, xb);
                    __half2 h2 = *(__half2*)&h;
                    Ahi[mt][ks * 4 + 0] = h;
                    Alo[mt][ks * 4 + 0] = packh(xa - __half2float(__low2half(h2)),
                                                xb - __half2float(__high2half(h2)));
                }
                // a1: row grp+8, k={k0,k0+1}
                xa = p1[(size_t)k0 * HW];        xb = p1[(size_t)(k0 + 1) * HW];
                s1 = fmaf(xa, xa, s1);           s1 = fmaf(xb, xb, s1);
                {
                    uint32_t h = packh(xa, xb);
                    __half2 h2 = *(__half2*)&h;
                    Ahi[mt][ks * 4 + 1] = h;
                    Alo[mt][ks * 4 + 1] = packh(xa - __half2float(__low2half(h2)),
                                                xb - __half2float(__high2half(h2)));
                }
                // a2: row grp, k={k0+8,k0+9}
                xa = p0[(size_t)(k0 + 8) * HW];  xb = p0[(size_t)(k0 + 9) * HW];
                s0 = fmaf(xa, xa, s0);           s0 = fmaf(xb, xb, s0);
                {
                    uint32_t h = packh(xa, xb);
                    __half2 h2 = *(__half2*)&h;
                    Ahi[mt][ks * 4 + 2] = h;
                    Alo[mt][ks * 4 + 2] = packh(xa - __half2float(__low2half(h2)),
                                                xb - __half2float(__high2half(h2)));
                }
                // a3: row grp+8, k={k0+8,k0+9}
                xa = p1[(size_t)(k0 + 8) * HW];  xb = p1[(size_t)(k0 + 9) * HW];
                s1 = fmaf(xa, xa, s1);           s1 = fmaf(xb, xb, s1);
                {
                    uint32_t h = packh(xa, xb);
                    __half2 h2 = *(__half2*)&h;
                    Ahi[mt][ks * 4 + 3] = h;
                    Alo[mt][ks * 4 + 3] = packh(xa - __half2float(__low2half(h2)),
                                                xb - __half2float(__high2half(h2)));
                }
            }
            // ssx: common-mode per token — sum the 4 cb4 lanes
            s0 += __shfl_xor_sync(0xffffffffu, s0, 1);
            s0 += __shfl_xor_sync(0xffffffffu, s0, 2);
            s1 += __shfl_xor_sync(0xffffffffu, s1, 1);
            s1 += __shfl_xor_sync(0xffffffffu, s1, 2);
            ssx[mt][0] = s0;
            ssx[mt][1] = s1;
        }

        float best[2][2] = {{3.4e38f, 3.4e38f}, {3.4e38f, 3.4e38f}};
        int   bidx[2][2] = {{0, 0}, {0, 0}};

        #pragma unroll 1
        for (int half = 0; half < 2; ++half) {
            __syncthreads();    // previous half (or prior p) consumers done
            // stage 512 codes' fragments (128KB), coalesced uint4
            const uint4* src = ((const uint4*)g_E) + half * 8192;
            #pragma unroll
            for (int i = 0; i < 32; ++i)
                sB[tid + i * 256] = src[tid + i * 256];
            __syncthreads();

            #pragma unroll 1
            for (int ng = 0; ng < 64; ng += 2) {
                float Chh[2][2][4], Cx[2][2][4];
                #pragma unroll
                for (int mt = 0; mt < 2; ++mt)
                    #pragma unroll
                    for (int u = 0; u < 2; ++u)
                        #pragma unroll
                        for (int v = 0; v < 4; ++v) {
                            Chh[mt][u][v] = 0.0f;
                            Cx[mt][u][v]  = 0.0f;
                        }

                #pragma unroll
                for (int ks = 0; ks < 4; ++ks) {
                    #pragma unroll
                    for (int u = 0; u < 2; ++u) {
                        uint4 B = sB[((ng + u) * 4 + ks) * 32 + lane];
                        #pragma unroll
                        for (int mt = 0; mt < 2; ++mt) {
                            mma_f16(Chh[mt][u], &Ahi[mt][ks * 4], B.x, B.y); // hi*hi
                            mma_f16(Cx[mt][u],  &Ahi[mt][ks * 4], B.z, B.w); // hi*lo
                            mma_f16(Cx[mt][u],  &Alo[mt][ks * 4], B.x, B.y); // lo*hi
                        }
                    }
                }

                #pragma unroll
                for (int u = 0; u < 2; ++u) {
                    const int kg = half * 512 + (ng + u) * 8 + 2 * cb4;
                    float2 ss = *(const float2*)&sSse[kg];
                    #pragma unroll
                    for (int mt = 0; mt < 2; ++mt) {
                        // scale-back by 2^-10 is exact
                        float c0 = (Chh[mt][u][0] + Cx[mt][u][0]) * EINV;
                        float c1 = (Chh[mt][u][1] + Cx[mt][u][1]) * EINV;
                        float c2 = (Chh[mt][u][2] + Cx[mt][u][2]) * EINV;
                        float c3 = (Chh[mt][u][3] + Cx[mt][u][3]) * EINV;
                        float d00 = (ssx[mt][0] + ss.x) - 2.0f * c0;
                        float d01 = (ssx[mt][0] + ss.y) - 2.0f * c1;
                        float d10 = (ssx[mt][1] + ss.x) - 2.0f * c2;
                        float d11 = (ssx[mt][1] + ss.y) - 2.0f * c3;
                        if (d00 < best[mt][0]) { best[mt][0] = d00; bidx[mt][0] = kg;     }
                        if (d01 < best[mt][0]) { best[mt][0] = d01; bidx[mt][0] = kg + 1; }
                        if (d10 < best[mt][1]) { best[mt][1] = d10; bidx[mt][1] = kg;     }
                        if (d11 < best[mt][1]) { best[mt][1] = d11; bidx[mt][1] = kg + 1; }
                    }
                }
            }
        }

        // reduce over the 4 cb4 lanes; ties -> lower index (global first-min)
        #pragma unroll
        for (int mt = 0; mt < 2; ++mt)
            #pragma unroll
            for (int h = 0; h < 2; ++h)
                #pragma unroll
                for (int o = 1; o <= 2; o <<= 1) {
                    float od = __shfl_xor_sync(0xffffffffu, best[mt][h], o);
                    int   oi = __shfl_xor_sync(0xffffffffu, bidx[mt][h], o);
                    if (od < best[mt][h] || (od == best[mt][h] && oi < bidx[mt][h])) {
                        best[mt][h] = od; bidx[mt][h] = oi;
                    }
                }

        // each lane writes one token: (mt, h) = (cb4>>1, cb4&1)
        {
            const int mymt = cb4 >> 1, myh = cb4 & 1;
            const int row  = base + mymt * 16 + grp + myh * 8;
            const int b    = row >> 12;
            const int hw   = row & (HW - 1);
            const int bi   = bidx[mymt][myh];
            const float4* e  = (const float4*)cb + bi * (D / 4);
            float*        op = out + (size_t)b * D * HW + hw;
            #pragma unroll
            for (int j = 0; j < D / 4; ++j) {
                float4 v = __ldg(e + j);
                op[(size_t)(4 * j + 0) * HW] = v.x;
                op[(size_t)(4 * j + 1) * HW] = v.y;
                op[(size_t)(4 * j + 2) * HW] = v.z;
                op[(size_t)(4 * j + 3) * HW] = v.w;
            }
        }
    }
}

extern "C" void kernel_launch(void* const* d_in, const int* in_sizes, int n_in,
                              void* d_out, int out_size) {
    const float* input    = (const float*)d_in[0];   // [16, 64, 64, 64] fp32 NCHW
    const float* codebook = (const float*)d_in[1];   // [1024, 64] fp32
    float*       out      = (float*)d_out;

    cudaFuncSetAttribute(vq_main, cudaFuncAttributeMaxDynamicSharedMemorySize, SMEM_REQ);
    vq_prep<<<64, 1024>>>(codebook);
    vq_main<<<128, 256, SMEM_REQ>>>(input, codebook, out);
}